// round 6
// baseline (speedup 1.0000x reference)
#include <cuda_runtime.h>
#include <cuda_bf16.h>
#include <math.h>
#include <stdint.h>

#define BB 8
#define CC 128
#define TT 8
#define HWD 1024
#define NPOS 8192
#define CT 1024

// ---------------- scratch ----------------
__device__ float g_qf[BB][128][HWD];
__device__ float g_kf[BB][128][HWD];
__device__ __nv_bfloat16 g_vf_h[BB][CT][HWD];
__device__ __nv_bfloat16 g_vf_l[BB][CT][HWD];
__device__ float g_attn[BB][HWD][HWD];
__device__ __nv_bfloat16 g_attn_h[BB][HWD][HWD];
__device__ __nv_bfloat16 g_attn_l[BB][HWD][HWD];
__device__ float g_ecam_p[32][BB][CC][CC];
__device__ float g_acam[BB][CC][CC];
__device__ float g_etim_p[BB][CC][36];
__device__ float g_atim[BB][TT][TT];

// ---------------- mma / cp.async helpers ----------------
__device__ __forceinline__ void mma16816(float* c, const uint32_t* a, const uint32_t* b) {
    asm volatile(
        "mma.sync.aligned.m16n8k16.row.col.f32.bf16.bf16.f32 "
        "{%0,%1,%2,%3}, {%4,%5,%6,%7}, {%8,%9}, {%0,%1,%2,%3};"
        : "+f"(c[0]), "+f"(c[1]), "+f"(c[2]), "+f"(c[3])
        : "r"(a[0]), "r"(a[1]), "r"(a[2]), "r"(a[3]), "r"(b[0]), "r"(b[1]));
}
__device__ __forceinline__ void mma_tf32(float* c, const uint32_t* a, const uint32_t* b) {
    asm volatile(
        "mma.sync.aligned.m16n8k8.row.col.f32.tf32.tf32.f32 "
        "{%0,%1,%2,%3}, {%4,%5,%6,%7}, {%8,%9}, {%0,%1,%2,%3};"
        : "+f"(c[0]), "+f"(c[1]), "+f"(c[2]), "+f"(c[3])
        : "r"(a[0]), "r"(a[1]), "r"(a[2]), "r"(a[3]), "r"(b[0]), "r"(b[1]));
}
__device__ __forceinline__ uint32_t f2tf32(float a) {
    uint32_t r; asm("cvt.rna.tf32.f32 %0, %1;" : "=r"(r) : "f"(a)); return r;
}
__device__ __forceinline__ void split_u(float a, uint32_t& h, uint32_t& l) {
    h = f2tf32(a);
    l = f2tf32(a - __uint_as_float(h));
}
__device__ __forceinline__ void split_tf32(float a, float& h, float& l) {
    uint32_t hu = f2tf32(a);
    h = __uint_as_float(hu);
    l = __uint_as_float(f2tf32(a - h));
}
__device__ __forceinline__ void split4(float4 v, float4& h, float4& l) {
    split_tf32(v.x, h.x, l.x);
    split_tf32(v.y, h.y, l.y);
    split_tf32(v.z, h.z, l.z);
    split_tf32(v.w, h.w, l.w);
}
__device__ __forceinline__ uint32_t smem_to_u32(const void* p) {
    uint32_t a;
    asm("{ .reg .u64 t; cvta.to.shared.u64 t, %1; cvt.u32.u64 %0, t; }" : "=r"(a) : "l"(p));
    return a;
}
__device__ __forceinline__ void cp16(uint32_t s, const void* g) {
    asm volatile("cp.async.cg.shared.global [%0], [%1], 16;"
                 :: "r"(s), "l"(__cvta_generic_to_global(g)) : "memory");
}
#define CP_COMMIT() asm volatile("cp.async.commit_group;" ::: "memory")
#define CP_WAIT(n)  asm volatile("cp.async.wait_group %0;" :: "n"(n) : "memory")

// ---------------- 1) fused q/k/v projection: tf32 MMA, cp.async x, frag-time split ----------------
// smem: Wh[2048] Wl[2048] | x stages 2 x (32*136)
#define QKV_SMEM_FLOATS (4096 + 2 * 4352)
#define QKV_SMEM_BYTES (QKV_SMEM_FLOATS * 4)
__global__ __launch_bounds__(256, 2) void k_qkv_tc(
    const float* __restrict__ x,
    const float* __restrict__ Wq, const float* __restrict__ bq,
    const float* __restrict__ Wk, const float* __restrict__ bk,
    const float* __restrict__ Wv, const float* __restrict__ bv)
{
    extern __shared__ float dsm[];
    float* Wh = dsm;
    float* Wl = dsm + 2048;
    float* Xst = dsm + 4096;
    uint32_t xsb = smem_to_u32(Xst);

    int b     = blockIdx.z;
    int rows0 = blockIdx.y * 64;
    int pos0  = blockIdx.x * 128;
    int tid = threadIdx.x, wid = tid >> 5, lane = tid & 31;
    int gid = lane >> 2, tq = lane & 3;
    int wm = (wid >> 1) * 16;
    int wn = (wid & 1) * 64;
    const float* xb = x + (size_t)b * (CC * NPOS);

    float acc[8][4] = {};

    auto load_x = [&](int st, int kc) {
#pragma unroll
        for (int q = 0; q < 4; q++) {
            int e = tid + q * 256;
            int f = e >> 5, ng = e & 31;
            uint32_t dst = xsb + (uint32_t)(st * 4352 + f * 136 + ng * 4) * 4;
            cp16(dst, xb + (size_t)(kc + f) * NPOS + pos0 + ng * 4);
        }
        CP_COMMIT();
    };

    load_x(0, 0);

    for (int it = 0; it < 4; it++) {
        int st = it & 1;
        int kc = it * 32;
        // W chunk (synchronous, small, pre-split)
#pragma unroll
        for (int q = 0; q < 2; q++) {
            int e = tid + q * 256;
            int row = e >> 3, c4 = e & 7;
            int r = rows0 + row;
            float4 v = make_float4(0.f, 0.f, 0.f, 0.f);
            if (r < 16)       v = *(const float4*)(Wq + r * 128 + kc + c4 * 4);
            else if (r < 32)  v = *(const float4*)(Wk + (r - 16) * 128 + kc + c4 * 4);
            else if (r < 160) v = *(const float4*)(Wv + (r - 32) * 128 + kc + c4 * 4);
            float4 h, l; split4(v, h, l);
            int so = row * 32 + ((c4 * 4) ^ ((row & 7) * 4));
            *(float4*)&Wh[so] = h;
            *(float4*)&Wl[so] = l;
        }
        if (it < 3) { load_x(st ^ 1, kc + 32); CP_WAIT(1); }
        else        { CP_WAIT(0); }
        __syncthreads();
        const float* Xr = Xst + st * 4352;

#pragma unroll
        for (int kk = 0; kk < 32; kk += 8) {
            uint32_t Af[4], Alf[4];
            int r0 = wm + gid, r1 = r0 + 8;
            int cA0 = kk + tq, cA1 = kk + tq + 4;
            Af[0]  = f2tf32(Wh[r0 * 32 + (cA0 ^ ((r0 & 7) * 4))]);
            Af[1]  = f2tf32(Wh[r1 * 32 + (cA0 ^ ((r1 & 7) * 4))]);
            Af[2]  = f2tf32(Wh[r0 * 32 + (cA1 ^ ((r0 & 7) * 4))]);
            Af[3]  = f2tf32(Wh[r1 * 32 + (cA1 ^ ((r1 & 7) * 4))]);
            Alf[0] = f2tf32(Wl[r0 * 32 + (cA0 ^ ((r0 & 7) * 4))]);
            Alf[1] = f2tf32(Wl[r1 * 32 + (cA0 ^ ((r1 & 7) * 4))]);
            Alf[2] = f2tf32(Wl[r0 * 32 + (cA1 ^ ((r0 & 7) * 4))]);
            Alf[3] = f2tf32(Wl[r1 * 32 + (cA1 ^ ((r1 & 7) * 4))]);
#pragma unroll
            for (int j = 0; j < 8; j++) {
                int n = wn + 8 * j + gid;
                uint32_t Bf[2], Blf[2];
                split_u(Xr[(kk + tq) * 136 + n],     Bf[0], Blf[0]);
                split_u(Xr[(kk + tq + 4) * 136 + n], Bf[1], Blf[1]);
                mma_tf32(acc[j], Af,  Bf);
                mma_tf32(acc[j], Af,  Blf);
                mma_tf32(acc[j], Alf, Bf);
            }
        }
        __syncthreads();
    }

    int t   = pos0 >> 10;
    int hw0 = pos0 & 1023;
#pragma unroll
    for (int j = 0; j < 8; j++) {
        int hw = hw0 + wn + 8 * j + 2 * tq;
#pragma unroll
        for (int half = 0; half < 2; half++) {
            int r = rows0 + wm + gid + half * 8;
            if (r >= 160) continue;
            float v0 = acc[j][half * 2 + 0];
            float v1 = acc[j][half * 2 + 1];
            if (r < 16) {
                float bias = bq[r];
                *(float2*)&g_qf[b][r * TT + t][hw] = make_float2(v0 + bias, v1 + bias);
            } else if (r < 32) {
                float bias = bk[r - 16];
                *(float2*)&g_kf[b][(r - 16) * TT + t][hw] = make_float2(v0 + bias, v1 + bias);
            } else {
                float bias = bv[r - 32];
                float a0 = v0 + bias, a1 = v1 + bias;
                __nv_bfloat16 h0 = __float2bfloat16(a0);
                __nv_bfloat16 l0 = __float2bfloat16(a0 - __bfloat162float(h0));
                __nv_bfloat16 h1 = __float2bfloat16(a1);
                __nv_bfloat16 l1 = __float2bfloat16(a1 - __bfloat162float(h1));
                int row = (r - 32) * TT + t;
                uint32_t hp = ((uint32_t)__bfloat16_as_ushort(h1) << 16) | __bfloat16_as_ushort(h0);
                uint32_t lp = ((uint32_t)__bfloat16_as_ushort(l1) << 16) | __bfloat16_as_ushort(l0);
                *(uint32_t*)&g_vf_h[b][row][hw] = hp;
                *(uint32_t*)&g_vf_l[b][row][hw] = lp;
            }
        }
    }
}

// ---------------- 2) PAM energy: tf32 MMA, cp.async 2-stage, frag-time split ----------------
// smem: 2 stages x (A 32*136 + B 32*136)
#define EN_SMEM_FLOATS (2 * 2 * 4352)
#define EN_SMEM_BYTES (EN_SMEM_FLOATS * 4)
__global__ __launch_bounds__(256, 2) void k_energy_tc()
{
    extern __shared__ float dsm[];
    uint32_t smb = smem_to_u32(dsm);

    int b  = blockIdx.z;
    int n0 = blockIdx.y * 128;
    int m0 = blockIdx.x * 128;
    int tid = threadIdx.x, wid = tid >> 5, lane = tid & 31;
    int gid = lane >> 2, tq = lane & 3;
    int wm = (wid >> 1) * 32;
    int wn = (wid & 1) * 64;

    float acc[2][8][4] = {};

    auto load_stage = [&](int st, int kc) {
#pragma unroll
        for (int q = 0; q < 4; q++) {
            int e = tid + q * 256;
            int f = e >> 5, ng = e & 31;
            uint32_t off = (uint32_t)(st * 8704 + f * 136 + ng * 4);
            cp16(smb + off * 4,              &g_qf[b][kc + f][n0 + ng * 4]);
            cp16(smb + (off + 4352) * 4,     &g_kf[b][kc + f][m0 + ng * 4]);
        }
        CP_COMMIT();
    };

    load_stage(0, 0);

    for (int it = 0; it < 4; it++) {
        int st = it & 1;
        if (it < 3) { load_stage(st ^ 1, (it + 1) * 32); CP_WAIT(1); }
        else        { CP_WAIT(0); }
        __syncthreads();
        const float* Ar = dsm + st * 8704;
        const float* Br = Ar + 4352;

#pragma unroll
        for (int kk = 0; kk < 32; kk += 8) {
            uint32_t Af[2][4], Alf[2][4];
#pragma unroll
            for (int i = 0; i < 2; i++) {
                int m = wm + 16 * i + gid;
                split_u(Ar[(kk + tq) * 136 + m],         Af[i][0], Alf[i][0]);
                split_u(Ar[(kk + tq) * 136 + m + 8],     Af[i][1], Alf[i][1]);
                split_u(Ar[(kk + tq + 4) * 136 + m],     Af[i][2], Alf[i][2]);
                split_u(Ar[(kk + tq + 4) * 136 + m + 8], Af[i][3], Alf[i][3]);
            }
#pragma unroll
            for (int j = 0; j < 8; j++) {
                int n = wn + 8 * j + gid;
                uint32_t Bf[2], Blf[2];
                split_u(Br[(kk + tq) * 136 + n],     Bf[0], Blf[0]);
                split_u(Br[(kk + tq + 4) * 136 + n], Bf[1], Blf[1]);
#pragma unroll
                for (int i = 0; i < 2; i++) {
                    mma_tf32(acc[i][j], Af[i],  Bf);
                    mma_tf32(acc[i][j], Af[i],  Blf);
                    mma_tf32(acc[i][j], Alf[i], Bf);
                }
            }
        }
        __syncthreads();
    }

#pragma unroll
    for (int i = 0; i < 2; i++)
#pragma unroll
        for (int j = 0; j < 8; j++) {
            int n = n0 + wm + 16 * i + gid;
            int m = m0 + wn + 8 * j + 2 * tq;
            *(float2*)&g_attn[b][n][m]     = make_float2(acc[i][j][0], acc[i][j][1]);
            *(float2*)&g_attn[b][n + 8][m] = make_float2(acc[i][j][2], acc[i][j][3]);
        }
}

// ---------------- 3) softmax -> bf16 hi/lo (vectorized) ----------------
__global__ __launch_bounds__(256) void k_softmax()
{
    int row = blockIdx.x;
    int tid = threadIdx.x;
    const float4* e4 = (const float4*)(&g_attn[0][0][0] + (size_t)row * 1024);
    float4 v = e4[tid];
    float m = fmaxf(fmaxf(v.x, v.y), fmaxf(v.z, v.w));
    __shared__ float red[8];
#pragma unroll
    for (int o = 16; o > 0; o >>= 1) m = fmaxf(m, __shfl_xor_sync(0xffffffffu, m, o));
    if ((tid & 31) == 0) red[tid >> 5] = m;
    __syncthreads();
    m = red[0];
#pragma unroll
    for (int j = 1; j < 8; j++) m = fmaxf(m, red[j]);
    v.x = __expf(v.x - m); v.y = __expf(v.y - m);
    v.z = __expf(v.z - m); v.w = __expf(v.w - m);
    float s = (v.x + v.y) + (v.z + v.w);
    __syncthreads();
#pragma unroll
    for (int o = 16; o > 0; o >>= 1) s += __shfl_xor_sync(0xffffffffu, s, o);
    if ((tid & 31) == 0) red[tid >> 5] = s;
    __syncthreads();
    s = red[0];
#pragma unroll
    for (int j = 1; j < 8; j++) s += red[j];
    float inv = 1.f / s;
    v.x *= inv; v.y *= inv; v.z *= inv; v.w *= inv;

    __nv_bfloat16 hx = __float2bfloat16(v.x), hy = __float2bfloat16(v.y);
    __nv_bfloat16 hz = __float2bfloat16(v.z), hw = __float2bfloat16(v.w);
    __nv_bfloat16 lx = __float2bfloat16(v.x - __bfloat162float(hx));
    __nv_bfloat16 ly = __float2bfloat16(v.y - __bfloat162float(hy));
    __nv_bfloat16 lz = __float2bfloat16(v.z - __bfloat162float(hz));
    __nv_bfloat16 lw = __float2bfloat16(v.w - __bfloat162float(hw));
    uint2 hp, lp;
    hp.x = ((uint32_t)__bfloat16_as_ushort(hy) << 16) | __bfloat16_as_ushort(hx);
    hp.y = ((uint32_t)__bfloat16_as_ushort(hw) << 16) | __bfloat16_as_ushort(hz);
    lp.x = ((uint32_t)__bfloat16_as_ushort(ly) << 16) | __bfloat16_as_ushort(lx);
    lp.y = ((uint32_t)__bfloat16_as_ushort(lw) << 16) | __bfloat16_as_ushort(lz);
    ((uint2*)(&g_attn_h[0][0][0] + (size_t)row * 1024))[tid] = hp;
    ((uint2*)(&g_attn_l[0][0][0] + (size_t)row * 1024))[tid] = lp;
}

// ---------------- 4) CAM energy: tf32 Gram, cp.async 2-stage, frag-time split ----------------
#define CAME_SMEM_BYTES (2 * 4096 * 4)
__global__ __launch_bounds__(256, 2) void k_came_tc(const float* __restrict__ x)
{
    extern __shared__ float cXr[];
    uint32_t smb = smem_to_u32(cXr);
    int b  = blockIdx.x >> 5;
    int sl = blockIdx.x & 31;
    int tid = threadIdx.x, wid = tid >> 5, lane = tid & 31;
    int gid = lane >> 2, tq = lane & 3;
    int wm = (wid >> 1) * 32;
    int wn = (wid & 1) * 64;
    const float* xb = x + (size_t)b * (CC * NPOS) + sl * 256;

    float acc[2][8][4] = {};

    auto load_stage = [&](int st, int kc) {
#pragma unroll
        for (int q = 0; q < 4; q++) {
            int e = tid + q * 256;
            int row = e >> 3, c4 = e & 7;
            uint32_t dst = smb + (uint32_t)(st * 4096 + row * 32 + ((c4 * 4) ^ ((row & 7) * 4))) * 4;
            cp16(dst, xb + (size_t)row * NPOS + kc + c4 * 4);
        }
        CP_COMMIT();
    };

    load_stage(0, 0);

    for (int it = 0; it < 8; it++) {
        int st = it & 1;
        if (it < 7) { load_stage(st ^ 1, (it + 1) * 32); CP_WAIT(1); }
        else        { CP_WAIT(0); }
        __syncthreads();
        const float* Xr = cXr + st * 4096;

#pragma unroll
        for (int kk = 0; kk < 32; kk += 8) {
            uint32_t Af[2][4], Alf[2][4];
            int c0 = kk + tq, c1 = kk + tq + 4;
#pragma unroll
            for (int i = 0; i < 2; i++) {
                int r0 = wm + 16 * i + gid, r1 = r0 + 8;
                split_u(Xr[r0 * 32 + (c0 ^ ((r0 & 7) * 4))], Af[i][0], Alf[i][0]);
                split_u(Xr[r1 * 32 + (c0 ^ ((r1 & 7) * 4))], Af[i][1], Alf[i][1]);
                split_u(Xr[r0 * 32 + (c1 ^ ((r0 & 7) * 4))], Af[i][2], Alf[i][2]);
                split_u(Xr[r1 * 32 + (c1 ^ ((r1 & 7) * 4))], Af[i][3], Alf[i][3]);
            }
#pragma unroll
            for (int j = 0; j < 8; j++) {
                int rn = wn + 8 * j + gid;
                uint32_t Bf[2], Blf[2];
                split_u(Xr[rn * 32 + (c0 ^ ((rn & 7) * 4))], Bf[0], Blf[0]);
                split_u(Xr[rn * 32 + (c1 ^ ((rn & 7) * 4))], Bf[1], Blf[1]);
#pragma unroll
                for (int i = 0; i < 2; i++) {
                    mma_tf32(acc[i][j], Af[i],  Bf);
                    mma_tf32(acc[i][j], Af[i],  Blf);
                    mma_tf32(acc[i][j], Alf[i], Bf);
                }
            }
        }
        __syncthreads();
    }

#pragma unroll
    for (int i = 0; i < 2; i++)
#pragma unroll
        for (int j = 0; j < 8; j++) {
            int c = wm + 16 * i + gid;
            int d = wn + 8 * j + 2 * tq;
            *(float2*)&g_ecam_p[sl][b][c][d]     = make_float2(acc[i][j][0], acc[i][j][1]);
            *(float2*)&g_ecam_p[sl][b][c + 8][d] = make_float2(acc[i][j][2], acc[i][j][3]);
        }
}

// ---------------- 5) CAM negated-energy softmax ----------------
__global__ __launch_bounds__(128) void k_camsm()
{
    int b = blockIdx.x >> 7;
    int c = blockIdx.x & 127;
    int d = threadIdx.x;
    float ev = 0.f;
#pragma unroll
    for (int sl = 0; sl < 32; sl++) ev += g_ecam_p[sl][b][c][d];
    __shared__ float red[4];
    float mn = ev;
#pragma unroll
    for (int o = 16; o > 0; o >>= 1) mn = fminf(mn, __shfl_xor_sync(0xffffffffu, mn, o));
    if ((threadIdx.x & 31) == 0) red[threadIdx.x >> 5] = mn;
    __syncthreads();
    mn = fminf(fminf(red[0], red[1]), fminf(red[2], red[3]));
    float w = __expf(mn - ev);
    __syncthreads();
    float s = w;
#pragma unroll
    for (int o = 16; o > 0; o >>= 1) s += __shfl_xor_sync(0xffffffffu, s, o);
    if ((threadIdx.x & 31) == 0) red[threadIdx.x >> 5] = s;
    __syncthreads();
    s = (red[0] + red[1]) + (red[2] + red[3]);
    g_acam[b][c][d] = w / s;
}

// ---------------- 6) TIM Gram partials ----------------
__global__ __launch_bounds__(256) void k_time(const float* __restrict__ x)
{
    int c = blockIdx.x;
    int b = blockIdx.y;
    int tid = threadIdx.x;
    const float* xp = x + ((size_t)b * CC + c) * NPOS;
    float v[8][4];
#pragma unroll
    for (int t = 0; t < 8; t++) {
        float4 f = *reinterpret_cast<const float4*>(xp + t * 1024 + tid * 4);
        v[t][0] = f.x; v[t][1] = f.y; v[t][2] = f.z; v[t][3] = f.w;
    }
    float acc[36];
    int idx = 0;
#pragma unroll
    for (int t = 0; t < 8; t++)
#pragma unroll
        for (int s = t; s < 8; s++) {
            float a = 0.f;
#pragma unroll
            for (int j = 0; j < 4; j++) a += v[t][j] * v[s][j];
            acc[idx++] = a;
        }
    __shared__ float red[36][8];
    int lane = tid & 31, warp = tid >> 5;
#pragma unroll
    for (int i = 0; i < 36; i++) {
        float a = acc[i];
#pragma unroll
        for (int o = 16; o > 0; o >>= 1) a += __shfl_xor_sync(0xffffffffu, a, o);
        if (lane == 0) red[i][warp] = a;
    }
    __syncthreads();
    if (tid < 36) {
        float a = 0.f;
#pragma unroll
        for (int w = 0; w < 8; w++) a += red[tid][w];
        g_etim_p[b][c][tid] = a;
    }
}

// ---------------- 7) TIM reduce + softmax ----------------
__global__ __launch_bounds__(256) void k_timsm()
{
    __shared__ float e36[BB][36];
    int tid = threadIdx.x;
    for (int o = tid; o < BB * 36; o += 256) {
        int b = o / 36, i = o % 36;
        float a = 0.f;
        for (int c = 0; c < CC; c++) a += g_etim_p[b][c][i];
        e36[b][i] = a;
    }
    __syncthreads();
    if (tid < 64) {
        int b = tid >> 3, t = tid & 7;
        float e[8];
#pragma unroll
        for (int s = 0; s < 8; s++) {
            int lo = t < s ? t : s, hi = t < s ? s : t;
            int idx = 8 * lo - lo * (lo - 1) / 2 + (hi - lo);
            e[s] = e36[b][idx];
        }
        float mn = e[0];
#pragma unroll
        for (int s = 1; s < 8; s++) mn = fminf(mn, e[s]);
        float w[8], sum = 0.f;
#pragma unroll
        for (int s = 0; s < 8; s++) { w[s] = __expf(mn - e[s]); sum += w[s]; }
#pragma unroll
        for (int s = 0; s < 8; s++) g_atim[b][t][s] = w[s] / sum;
    }
}

// ---------------- 8) base: out = 3x + gc*(a_cam@xc) + gt*tim (x read once) ----------------
__global__ __launch_bounds__(256) void k_base(
    const float* __restrict__ x,
    const float* __restrict__ gcp, const float* __restrict__ gtp,
    float* __restrict__ out)
{
    int b   = blockIdx.z;
    int c0  = blockIdx.y * 32;
    int hw0 = blockIdx.x * 32;
    __shared__ float As[32][33];
    __shared__ float Xs[32][8][33];
    __shared__ float at8[8][8];
    int tid = threadIdx.x;
    int hw_l = tid & 31, cg = tid >> 5;
    if (tid < 64) at8[tid >> 3][tid & 7] = g_atim[b][tid >> 3][tid & 7];
    float acc[4][8] = {};
    float xr[4][8];
    const float* xb = x + (size_t)b * (CC * NPOS);

    for (int kc = 0; kc < CC; kc += 32) {
#pragma unroll
        for (int q = 0; q < 4; q++) {
            int e = tid + q * 256;
            int i = e >> 5, k = e & 31;
            As[i][k] = g_acam[b][c0 + i][kc + k];
        }
#pragma unroll
        for (int q = 0; q < 32; q++) {
            int e = tid + q * 256;
            int k = e >> 8, t = (e >> 5) & 7, hw = e & 31;
            Xs[k][t][hw] = xb[(size_t)(kc + k) * NPOS + t * 1024 + hw0 + hw];
        }
        __syncthreads();
        if (kc == c0) {
            // harvest this CTA's own channel rows for the epilogue
#pragma unroll
            for (int j = 0; j < 4; j++)
#pragma unroll
                for (int t = 0; t < 8; t++) xr[j][t] = Xs[cg + 8 * j][t][hw_l];
        }
#pragma unroll
        for (int k = 0; k < 32; k++) {
            float av[4], xv[8];
#pragma unroll
            for (int j = 0; j < 4; j++) av[j] = As[cg + 8 * j][k];
#pragma unroll
            for (int t = 0; t < 8; t++) xv[t] = Xs[k][t][hw_l];
#pragma unroll
            for (int j = 0; j < 4; j++)
#pragma unroll
                for (int t = 0; t < 8; t++) acc[j][t] += av[j] * xv[t];
        }
        __syncthreads();
    }

    float gc = gcp[0], gt = gtp[0];
#pragma unroll
    for (int j = 0; j < 4; j++) {
        int c = c0 + cg + 8 * j;
        float* oc = out + (size_t)b * (CC * NPOS) + (size_t)c * NPOS + hw0 + hw_l;
#pragma unroll
        for (int t = 0; t < 8; t++) {
            float tim = 0.f;
#pragma unroll
            for (int s = 0; s < 8; s++) tim += at8[t][s] * xr[j][s];
            oc[t * 1024] = 3.f * xr[j][t] + gc * acc[j][t] + gt * tim;
        }
    }
}

// ---------------- 9) PAM GEMM via mma.sync bf16x3, cp.async 2-stage ----------------
#define PAD 40
#define PAM_STAGE_ELTS 20480
#define PAM_SMEM_BYTES (2 * PAM_STAGE_ELTS * 2)
__global__ __launch_bounds__(256, 2) void k_pam_mma(const float* __restrict__ gpp,
                                                    float* __restrict__ out)
{
    extern __shared__ __nv_bfloat16 smp[];
    uint32_t smb = smem_to_u32(smp);

    int tid = threadIdx.x;
    int b  = blockIdx.z;
    int r0 = blockIdx.y * 128;
    int n0 = blockIdx.x * 128;
    int wid = tid >> 5, lane = tid & 31;
    int gid = lane >> 2, tq = lane & 3;
    int wm = (wid & 1) * 64;
    int wn = (wid >> 1) * 32;

    const __nv_bfloat16* Ahp = &g_vf_h[b][0][0];
    const __nv_bfloat16* Alp = &g_vf_l[b][0][0];
    const __nv_bfloat16* Bhp = &g_attn_h[b][0][0];
    const __nv_bfloat16* Blp = &g_attn_l[b][0][0];

    float acc[4][4][4] = {};

    auto stage_load = [&](int st, int kc) {
#pragma unroll
        for (int q = 0; q < 2; q++) {
            int e = tid + q * 256;
            int row = e >> 2, c4 = e & 3;
            uint32_t so = smb + (uint32_t)(st * PAM_STAGE_ELTS + row * PAD + c4 * 8) * 2;
            size_t gA = (size_t)(r0 + row) * 1024 + kc + c4 * 8;
            size_t gB = (size_t)(n0 + row) * 1024 + kc + c4 * 8;
            cp16(so,              Ahp + gA);
            cp16(so + 5120 * 2,   Alp + gA);
            cp16(so + 10240 * 2,  Bhp + gB);
            cp16(so + 15360 * 2,  Blp + gB);
        }
        CP_COMMIT();
    };

    stage_load(0, 0);

    for (int it = 0; it < 32; it++) {
        int st = it & 1;
        if (it < 31) { stage_load(st ^ 1, (it + 1) * 32); CP_WAIT(1); }
        else         { CP_WAIT(0); }
        __syncthreads();

        const __nv_bfloat16* sAh = smp + st * PAM_STAGE_ELTS;
        const __nv_bfloat16* sAl = sAh + 5120;
        const __nv_bfloat16* sBh = sAh + 10240;
        const __nv_bfloat16* sBl = sAh + 15360;

#pragma unroll
        for (int ks = 0; ks < 32; ks += 16) {
            uint32_t Af[4][4], Alf[4][4];
            int col = ks + tq * 2;
#pragma unroll
            for (int i = 0; i < 4; i++) {
                int row = wm + 16 * i + gid;
                Af[i][0]  = *(const uint32_t*)&sAh[row * PAD + col];
                Af[i][1]  = *(const uint32_t*)&sAh[(row + 8) * PAD + col];
                Af[i][2]  = *(const uint32_t*)&sAh[row * PAD + col + 8];
                Af[i][3]  = *(const uint32_t*)&sAh[(row + 8) * PAD + col + 8];
                Alf[i][0] = *(const uint32_t*)&sAl[row * PAD + col];
                Alf[i][1] = *(const uint32_t*)&sAl[(row + 8) * PAD + col];
                Alf[i][2] = *(const uint32_t*)&sAl[row * PAD + col + 8];
                Alf[i][3] = *(const uint32_t*)&sAl[(row + 8) * PAD + col + 8];
            }
#pragma unroll
            for (int j = 0; j < 4; j++) {
                int nrow = wn + 8 * j + gid;
                uint32_t Bf[2], Blf[2];
                Bf[0]  = *(const uint32_t*)&sBh[nrow * PAD + col];
                Bf[1]  = *(const uint32_t*)&sBh[nrow * PAD + col + 8];
                Blf[0] = *(const uint32_t*)&sBl[nrow * PAD + col];
                Blf[1] = *(const uint32_t*)&sBl[nrow * PAD + col + 8];
#pragma unroll
                for (int i = 0; i < 4; i++) {
                    mma16816(acc[i][j], Af[i],  Bf);
                    mma16816(acc[i][j], Af[i],  Blf);
                    mma16816(acc[i][j], Alf[i], Bf);
                }
            }
        }
        __syncthreads();
    }

    float gpv = gpp[0];
    float* ob = out + (size_t)b * (CT * HWD);
#pragma unroll
    for (int i = 0; i < 4; i++) {
#pragma unroll
        for (int j = 0; j < 4; j++) {
            int r = r0 + wm + 16 * i + gid;
            int n = n0 + wn + 8 * j + tq * 2;
            float2* p0 = (float2*)(ob + (size_t)r * 1024 + n);
            float2 v0 = *p0;
            v0.x += gpv * acc[i][j][0];
            v0.y += gpv * acc[i][j][1];
            *p0 = v0;
            float2* p1 = (float2*)(ob + (size_t)(r + 8) * 1024 + n);
            float2 v1 = *p1;
            v1.x += gpv * acc[i][j][2];
            v1.y += gpv * acc[i][j][3];
            *p1 = v1;
        }
    }
}

// ---------------- launch ----------------
extern "C" void kernel_launch(void* const* d_in, const int* in_sizes, int n_in,
                              void* d_out, int out_size)
{
    const float* x  = (const float*)d_in[0];
    const float* Wq = (const float*)d_in[1];
    const float* bq = (const float*)d_in[2];
    const float* Wk = (const float*)d_in[3];
    const float* bk = (const float*)d_in[4];
    const float* Wv = (const float*)d_in[5];
    const float* bv = (const float*)d_in[6];
    const float* gp = (const float*)d_in[7];
    const float* gc = (const float*)d_in[8];
    const float* gt = (const float*)d_in[9];
    float* out = (float*)d_out;

    static int attrs_set = 0;
    if (!attrs_set) {
        cudaFuncSetAttribute(k_qkv_tc, cudaFuncAttributeMaxDynamicSharedMemorySize, QKV_SMEM_BYTES);
        cudaFuncSetAttribute(k_energy_tc, cudaFuncAttributeMaxDynamicSharedMemorySize, EN_SMEM_BYTES);
        cudaFuncSetAttribute(k_came_tc, cudaFuncAttributeMaxDynamicSharedMemorySize, CAME_SMEM_BYTES);
        cudaFuncSetAttribute(k_pam_mma, cudaFuncAttributeMaxDynamicSharedMemorySize, PAM_SMEM_BYTES);
        attrs_set = 1;
    }

    k_qkv_tc<<<dim3(64, 3, 8), 256, QKV_SMEM_BYTES>>>(x, Wq, bq, Wk, bk, Wv, bv);
    k_energy_tc<<<dim3(8, 8, 8), 256, EN_SMEM_BYTES>>>();
    k_softmax<<<8192, 256>>>();
    k_came_tc<<<256, 256, CAME_SMEM_BYTES>>>(x);
    k_camsm<<<1024, 128>>>();
    k_time<<<dim3(128, 8), 256>>>(x);
    k_timsm<<<1, 256>>>();
    k_base<<<dim3(32, 4, 8), 256>>>(x, gc, gt, out);
    k_pam_mma<<<dim3(8, 8, 8), 256, PAM_SMEM_BYTES>>>(gp, out);
}